// round 12
// baseline (speedup 1.0000x reference)
#include <cuda_runtime.h>
#include <cuda_bf16.h>
#include <cstdint>

constexpr int NPIX = 4096;
#define DEVI static __device__ __forceinline__

// bf16 scratch: q[B,N,32] (pre-scaled by log2e), k[B,N,32], v CHANNEL-MAJOR [B,256,N]
__device__ __nv_bfloat16 g_q[(size_t)4 * 4096 * 32];
__device__ __nv_bfloat16 g_k[(size_t)4 * 4096 * 32];
__device__ __nv_bfloat16 g_v[(size_t)4 * 256 * 4096];
// bf16 weights, chunk-major [ic][rows][64]
__device__ __nv_bfloat16 g_wv[8 * 256 * 64];
__device__ __nv_bfloat16 g_wq[8 * 32 * 64];   // pre-scaled by log2e
__device__ __nv_bfloat16 g_wk[4 * 32 * 64];

DEVI uint32_t su(const void* p) { return (uint32_t)__cvta_generic_to_shared(p); }
DEVI void ldsm4(uint32_t& r0, uint32_t& r1, uint32_t& r2, uint32_t& r3, uint32_t a) {
    asm volatile("ldmatrix.sync.aligned.m8n8.x4.shared.b16 {%0,%1,%2,%3},[%4];"
                 : "=r"(r0), "=r"(r1), "=r"(r2), "=r"(r3) : "r"(a));
}
DEVI void ldsm4t(uint32_t& r0, uint32_t& r1, uint32_t& r2, uint32_t& r3, uint32_t a) {
    asm volatile("ldmatrix.sync.aligned.m8n8.x4.trans.shared.b16 {%0,%1,%2,%3},[%4];"
                 : "=r"(r0), "=r"(r1), "=r"(r2), "=r"(r3) : "r"(a));
}
DEVI void mma16816(float* c, const uint32_t* a, uint32_t b0, uint32_t b1) {
    asm volatile("mma.sync.aligned.m16n8k16.row.col.f32.bf16.bf16.f32 "
                 "{%0,%1,%2,%3},{%4,%5,%6,%7},{%8,%9},{%0,%1,%2,%3};"
                 : "+f"(c[0]), "+f"(c[1]), "+f"(c[2]), "+f"(c[3])
                 : "r"(a[0]), "r"(a[1]), "r"(a[2]), "r"(a[3]), "r"(b0), "r"(b1));
}
DEVI void cp16(uint32_t s, const void* g) {
    asm volatile("cp.async.cg.shared.global [%0],[%1],16;" ::"r"(s), "l"(g));
}
DEVI void cp_commit() { asm volatile("cp.async.commit_group;" ::: "memory"); }
template <int NN> DEVI void cp_wait() { asm volatile("cp.async.wait_group %0;" ::"n"(NN) : "memory"); }
DEVI float ex2f(float x) { float r; asm("ex2.approx.f32 %0,%1;" : "=f"(r) : "f"(x)); return r; }
DEVI uint32_t packbf2(float a, float b) {
    __nv_bfloat162 h = __floats2bfloat162_rn(a, b);
    return *reinterpret_cast<uint32_t*>(&h);
}
DEVI void bar384() { asm volatile("bar.sync 1, 384;" ::: "memory"); }
DEVI void bar256pv() { asm volatile("bar.sync 2, 256;" ::: "memory"); }

// ===========================================================================
// Prep: fp32 weights -> bf16 chunk-major scratch. Qw scaled by log2e.
// ===========================================================================
__global__ __launch_bounds__(256) void prep_kernel(
    const float* __restrict__ Qw, const float* __restrict__ Kw, const float* __restrict__ Vw)
{
    const float L = 1.4426950408889634f;
    int i = blockIdx.x * 256 + threadIdx.x;
    {
        int ic = i >> 12, rem = i & 4095, r = rem >> 4, j4 = (rem & 15) * 4;
        float4 v = *(const float4*)(Vw + (size_t)r * 512 + ic * 64 + j4);
        *(uint2*)(g_wv + ic * 16384 + r * 64 + j4) =
            make_uint2(packbf2(v.x, v.y), packbf2(v.z, v.w));
    }
    if (i < 4096) {
        int ic = i >> 9, rem = i & 511, r = rem >> 4, j4 = (rem & 15) * 4;
        float4 v = *(const float4*)(Qw + (size_t)r * 512 + ic * 64 + j4);
        *(uint2*)(g_wq + ic * 2048 + r * 64 + j4) =
            make_uint2(packbf2(v.x * L, v.y * L), packbf2(v.z * L, v.w * L));
    }
    if (i < 2048) {
        int ic = i >> 9, rem = i & 511, r = rem >> 4, j4 = (rem & 15) * 4;
        float4 v = *(const float4*)(Kw + (size_t)r * 256 + ic * 64 + j4);
        *(uint2*)(g_wk + ic * 2048 + r * 64 + j4) =
            make_uint2(packbf2(v.x, v.y), packbf2(v.z, v.w));
    }
}

// ===========================================================================
// Projection (HMMA). block = (m-tile 128, batch). Writes q/k row-major,
// v CHANNEL-MAJOR via smem transpose. (unchanged)
// ===========================================================================
constexpr int PROJ_SMEM = (64 * 136 * 2) * 2 + 256 * 72 * 2 + 32 * 72 * 2 * 2;  // 80896

__global__ __launch_bounds__(256, 1) void proj_kernel(
    const float* __restrict__ ef, const float* __restrict__ sf, const float* __restrict__ attn,
    const float* __restrict__ Qb, const float* __restrict__ Kb, const float* __restrict__ Vb)
{
    extern __shared__ __align__(16) char smem_raw[];
    __nv_bfloat16* Xc = (__nv_bfloat16*)smem_raw;
    __nv_bfloat16* Ac = Xc + 64 * 136;
    __nv_bfloat16* Wv = Ac + 64 * 136;
    __nv_bfloat16* Wq = Wv + 256 * 72;
    __nv_bfloat16* Wk = Wq + 32 * 72;

    const int b = blockIdx.y, m0 = blockIdx.x * 128;
    const int tid = threadIdx.x, lane = tid & 31, warp = tid >> 5, mw = warp * 16;

    float ov[128], oq[16], ok[16];
#pragma unroll
    for (int i = 0; i < 128; i++) ov[i] = 0.f;
#pragma unroll
    for (int i = 0; i < 16; i++) { oq[i] = 0.f; ok[i] = 0.f; }

#pragma unroll 1
    for (int ic = 0; ic < 8; ic++) {
        const int i0 = ic * 64;
        __syncthreads();
        {
            const __nv_bfloat16* wv = g_wv + ic * 16384;
#pragma unroll
            for (int t = 0; t < 8; t++) {
                int idx = tid + t * 256, r = idx >> 3, seg = idx & 7;
                cp16(su(Wv + r * 72 + seg * 8), wv + r * 64 + seg * 8);
            }
            const __nv_bfloat16* wq = g_wq + ic * 2048;
            { int r = tid >> 3, seg = tid & 7;
              cp16(su(Wq + r * 72 + seg * 8), wq + r * 64 + seg * 8); }
            if (ic < 4) {
                const __nv_bfloat16* wk = g_wk + ic * 2048;
                int r = tid >> 3, seg = tid & 7;
                cp16(su(Wk + r * 72 + seg * 8), wk + r * 64 + seg * 8);
            }
            cp_commit();
        }
#pragma unroll
        for (int t = 0; t < 8; t++) {
            int idx = tid + t * 256, il = idx >> 5, j = (idx & 31) * 4;
            int gi = i0 + il;
            const float* src = (gi < 256) ? (ef + ((size_t)(b * 256 + gi)) * NPIX + m0 + j)
                                          : (sf + ((size_t)(b * 256 + gi - 256)) * NPIX + m0 + j);
            float4 v = *(const float4*)src;
            *(uint2*)(Xc + il * 136 + j) = make_uint2(packbf2(v.x, v.y), packbf2(v.z, v.w));
        }
        if (ic < 4) {
#pragma unroll
            for (int t = 0; t < 8; t++) {
                int idx = tid + t * 256, il = idx >> 5, j = (idx & 31) * 4;
                float4 v = *(const float4*)(attn + ((size_t)(b * 256 + i0 + il)) * NPIX + m0 + j);
                *(uint2*)(Ac + il * 136 + j) = make_uint2(packbf2(v.x, v.y), packbf2(v.z, v.w));
            }
        }
        cp_wait<0>();
        __syncthreads();

#pragma unroll
        for (int kt = 0; kt < 4; kt++) {
            const int k0 = kt * 16;
            uint32_t xa[4];
            ldsm4t(xa[0], xa[1], xa[2], xa[3],
                su(Xc + (k0 + (lane & 7) + ((lane >> 4) << 3)) * 136 + mw + (((lane >> 3) & 1) << 3)));
#pragma unroll
            for (int cp = 0; cp < 16; cp++) {
                uint32_t b0, b1, b2, b3;
                ldsm4(b0, b1, b2, b3, su(Wv + ((cp << 4) + (lane & 15)) * 72 + k0 + ((lane >> 4) << 3)));
                mma16816(ov + cp * 8, xa, b0, b2);
                mma16816(ov + cp * 8 + 4, xa, b1, b3);
            }
            {
                uint32_t b0, b1, b2, b3;
                ldsm4(b0, b1, b2, b3, su(Wq + (lane & 15) * 72 + k0 + ((lane >> 4) << 3)));
                mma16816(oq + 0, xa, b0, b2);
                mma16816(oq + 4, xa, b1, b3);
                ldsm4(b0, b1, b2, b3, su(Wq + (16 + (lane & 15)) * 72 + k0 + ((lane >> 4) << 3)));
                mma16816(oq + 8, xa, b0, b2);
                mma16816(oq + 12, xa, b1, b3);
            }
            if (ic < 4) {
                uint32_t aa[4];
                ldsm4t(aa[0], aa[1], aa[2], aa[3],
                    su(Ac + (k0 + (lane & 7) + ((lane >> 4) << 3)) * 136 + mw + (((lane >> 3) & 1) << 3)));
                uint32_t b0, b1, b2, b3;
                ldsm4(b0, b1, b2, b3, su(Wk + (lane & 15) * 72 + k0 + ((lane >> 4) << 3)));
                mma16816(ok + 0, aa, b0, b2);
                mma16816(ok + 4, aa, b1, b3);
                ldsm4(b0, b1, b2, b3, su(Wk + (16 + (lane & 15)) * 72 + k0 + ((lane >> 4) << 3)));
                mma16816(ok + 8, aa, b0, b2);
                mma16816(ok + 12, aa, b1, b3);
            }
        }
    }

    const float L = 1.4426950408889634f;
    const int r0 = m0 + mw + (lane >> 2), cb = (lane & 3) * 2;
#pragma unroll
    for (int dt = 0; dt < 4; dt++) {
        int d = dt * 8 + cb;
        float bq0 = Qb[d] * L, bq1 = Qb[d + 1] * L;
        *(uint32_t*)&g_q[((size_t)(b * NPIX + r0)) * 32 + d]     = packbf2(oq[dt * 4 + 0] + bq0, oq[dt * 4 + 1] + bq1);
        *(uint32_t*)&g_q[((size_t)(b * NPIX + r0 + 8)) * 32 + d] = packbf2(oq[dt * 4 + 2] + bq0, oq[dt * 4 + 3] + bq1);
        float bk0 = Kb[d], bk1 = Kb[d + 1];
        *(uint32_t*)&g_k[((size_t)(b * NPIX + r0)) * 32 + d]     = packbf2(ok[dt * 4 + 0] + bk0, ok[dt * 4 + 1] + bk1);
        *(uint32_t*)&g_k[((size_t)(b * NPIX + r0 + 8)) * 32 + d] = packbf2(ok[dt * 4 + 2] + bk0, ok[dt * 4 + 3] + bk1);
    }
    __syncthreads();
    __nv_bfloat16* Vt = (__nv_bfloat16*)smem_raw;   // [256][136]
    const int rl = mw + (lane >> 2);
#pragma unroll
    for (int ct = 0; ct < 32; ct++) {
        int c = ct * 8 + cb;
        float bb0 = Vb[c], bb1 = Vb[c + 1];
        Vt[c * 136 + rl]           = __float2bfloat16(ov[ct * 4 + 0] + bb0);
        Vt[(c + 1) * 136 + rl]     = __float2bfloat16(ov[ct * 4 + 1] + bb1);
        Vt[c * 136 + rl + 8]       = __float2bfloat16(ov[ct * 4 + 2] + bb0);
        Vt[(c + 1) * 136 + rl + 8] = __float2bfloat16(ov[ct * 4 + 3] + bb1);
    }
    __syncthreads();
#pragma unroll
    for (int t = 0; t < 16; t++) {
        int i = tid + t * 256;
        int c = i >> 4, seg = i & 15;
        *(uint4*)(g_v + ((size_t)(b * 256 + c)) * NPIX + m0 + seg * 8) =
            *(uint4*)(Vt + c * 136 + seg * 8);
    }
}

// ===========================================================================
// Flash attention, warp-specialized HMMA, O computed TRANSPOSED:
//   O^T[c][m] = V[c][n] * P[m][n]^T   (A = V rows c, B = P rows m; no trans ldsm)
// warps 0-3 = S (QK^T + exp2 -> P smem rows m + row sums Ls[m])
// warps 4-11 = PV; warp pw owns channels [pw*32, pw*32+32) x all 128 m.
// smem: Qs[128][40] | Ks[2][64][40] | Vt[3][256][72] | Ps[2][128][72] | Ls[128] | invLs[128]
// ===========================================================================
constexpr int FS_Q = 0;
constexpr int FS_K = FS_Q + 128 * 40 * 2;           // 10240
constexpr int FS_V = FS_K + 2 * 64 * 40 * 2;        // 20480
constexpr int FS_P = FS_V + 3 * 256 * 72 * 2;       // 131072
constexpr int FS_L = FS_P + 2 * 128 * 72 * 2;       // 167936
constexpr int FS_I = FS_L + 512;                    // 168448
constexpr int FLASH_SMEM = FS_I + 512;              // 168960

__global__ __launch_bounds__(384, 1)
void flash_kernel(const float* __restrict__ ef, const float* __restrict__ gamma_p,
                  float* __restrict__ out)
{
    extern __shared__ __align__(16) char smem[];
    __nv_bfloat16* Qs = (__nv_bfloat16*)(smem + FS_Q);
    __nv_bfloat16* Ks = (__nv_bfloat16*)(smem + FS_K);
    __nv_bfloat16* Vt = (__nv_bfloat16*)(smem + FS_V);
    __nv_bfloat16* Ps = (__nv_bfloat16*)(smem + FS_P);
    float* Ls = (float*)(smem + FS_L);
    float* invLs = (float*)(smem + FS_I);

    const int b = blockIdx.y, mtile = blockIdx.x * 128;
    const int tid = threadIdx.x, lane = tid & 31, warp = tid >> 5;

    const __nv_bfloat16* gq = g_q + (size_t)b * NPIX * 32;
    const __nv_bfloat16* gk = g_k + (size_t)b * NPIX * 32;
    const __nv_bfloat16* gv = g_v + (size_t)b * 256 * NPIX;   // [256][4096]

    // initial loads: Q (full), K(0), V(0)
#pragma unroll
    for (int t = 0; t < 2; t++) {
        int idx = tid + t * 384;
        if (idx < 512) {
            int r = idx >> 2, sg = idx & 3;
            cp16(su(Qs + r * 40 + sg * 8), gq + (size_t)(mtile + r) * 32 + sg * 8);
        }
    }
    if (tid < 256) {
        int r = tid >> 2, sg = tid & 3;
        cp16(su(Ks + r * 40 + sg * 8), gk + (size_t)r * 32 + sg * 8);
    }
#pragma unroll
    for (int t = 0; t < 6; t++) {
        int idx = tid + t * 384;
        if (idx < 2048) {
            int c = idx >> 3, sg = idx & 7;
            cp16(su(Vt + c * 72 + sg * 8), gv + (size_t)c * NPIX + sg * 8);
        }
    }
    cp_commit();

    if (warp < 4) {
        // ------------------- S warps -------------------
        const int mt = warp * 32;
        uint32_t qa[2][2][4];
        float l4[4] = {0.f, 0.f, 0.f, 0.f};
#pragma unroll 1
        for (int nt = 0; nt < 64; nt++) {
            const int buf = nt & 1;
            if (nt + 1 < 64) {
                const int n0 = (nt + 1) * 64, kb = (nt + 1) & 1;
#pragma unroll
                for (int t = 0; t < 2; t++) {
                    int idx = tid + t * 128;
                    int r = idx >> 2, sg = idx & 3;
                    cp16(su(Ks + kb * 2560 + r * 40 + sg * 8),
                         gk + (size_t)(n0 + r) * 32 + sg * 8);
                }
                cp_commit();
                cp_wait<1>();
            } else cp_wait<0>();
            bar384();
            if (nt == 0) {
#pragma unroll
                for (int mi = 0; mi < 2; mi++)
#pragma unroll
                    for (int kt = 0; kt < 2; kt++)
                        ldsm4(qa[mi][kt][0], qa[mi][kt][1], qa[mi][kt][2], qa[mi][kt][3],
                            su(Qs + (mt + mi * 16 + (lane & 15)) * 40 + kt * 16 + ((lane >> 4) << 3)));
            }
            float s[2][32];
#pragma unroll
            for (int mi = 0; mi < 2; mi++)
#pragma unroll
                for (int i = 0; i < 32; i++) s[mi][i] = 0.f;
            const __nv_bfloat16* Kb_ = Ks + buf * 2560;
#pragma unroll
            for (int jp = 0; jp < 4; jp++)
#pragma unroll
                for (int kt = 0; kt < 2; kt++) {
                    uint32_t r0, r1, r2, r3;
                    ldsm4(r0, r1, r2, r3,
                        su(Kb_ + (jp * 16 + (lane & 15)) * 40 + kt * 16 + ((lane >> 4) << 3)));
#pragma unroll
                    for (int mi = 0; mi < 2; mi++) {
                        mma16816(s[mi] + jp * 8,     qa[mi][kt], r0, r2);
                        mma16816(s[mi] + jp * 8 + 4, qa[mi][kt], r1, r3);
                    }
                }
            __nv_bfloat16* Pb = Ps + buf * 9216;
#pragma unroll
            for (int mi = 0; mi < 2; mi++) {
                __nv_bfloat16* pr = Pb + (mt + mi * 16 + (lane >> 2)) * 72 + (lane & 3) * 2;
#pragma unroll
                for (int j = 0; j < 8; j++) {
                    float p0 = ex2f(s[mi][j * 4 + 0]), p1 = ex2f(s[mi][j * 4 + 1]);
                    float p2 = ex2f(s[mi][j * 4 + 2]), p3 = ex2f(s[mi][j * 4 + 3]);
                    l4[mi * 2 + 0] += p0 + p1;
                    l4[mi * 2 + 1] += p2 + p3;
                    *(uint32_t*)(pr + j * 8)          = packbf2(p0, p1);
                    *(uint32_t*)(pr + 8 * 72 + j * 8) = packbf2(p2, p3);
                }
            }
        }
#pragma unroll
        for (int i = 0; i < 4; i++) {
            l4[i] += __shfl_xor_sync(~0u, l4[i], 1);
            l4[i] += __shfl_xor_sync(~0u, l4[i], 2);
        }
        if ((lane & 3) == 0) {
            Ls[mt + (lane >> 2)]      = l4[0];
            Ls[mt + 8 + (lane >> 2)]  = l4[1];
            Ls[mt + 16 + (lane >> 2)] = l4[2];
            Ls[mt + 24 + (lane >> 2)] = l4[3];
        }
        bar384();   // release P(63) + Ls to PV warps
    } else {
        // ------------------- PV warps (O^T) -------------------
        const int pw = warp - 4;
        const int tid2 = tid - 128;
        float o[128];   // o[mi*64 + nj*8 + half*4 + e]
#pragma unroll
        for (int i = 0; i < 128; i++) o[i] = 0.f;
#pragma unroll 1
        for (int nt = 0; nt <= 64; nt++) {
            if (nt + 1 < 64) {
                const int n0 = (nt + 1) * 64, vb = (nt + 1) % 3;
#pragma unroll
                for (int t = 0; t < 8; t++) {
                    int idx = tid2 + t * 256;
                    int c = idx >> 3, sg = idx & 7;
                    cp16(su(Vt + vb * 18432 + c * 72 + sg * 8),
                         gv + (size_t)c * NPIX + n0 + sg * 8);
                }
                cp_commit();
                cp_wait<1>();
            } else cp_wait<0>();
            bar384();
            if (nt == 0) continue;
            const int j = nt - 1, pbuf = j & 1, vbuf = j % 3;
            const __nv_bfloat16* Pb = Ps + pbuf * 9216;
            const __nv_bfloat16* Vb_ = Vt + vbuf * 18432;
#pragma unroll
            for (int kt = 0; kt < 4; kt++) {
                uint32_t av[2][4];
#pragma unroll
                for (int mi = 0; mi < 2; mi++)
                    ldsm4(av[mi][0], av[mi][1], av[mi][2], av[mi][3],
                        su(Vb_ + (pw * 32 + mi * 16 + (lane & 15)) * 72 + kt * 16 + ((lane >> 4) << 3)));
#pragma unroll
                for (int nj = 0; nj < 8; nj++) {
                    uint32_t b0, b1, b2, b3;
                    ldsm4(b0, b1, b2, b3,
                        su(Pb + (nj * 16 + (lane & 15)) * 72 + kt * 16 + ((lane >> 4) << 3)));
#pragma unroll
                    for (int mi = 0; mi < 2; mi++) {
                        mma16816(o + mi * 64 + nj * 8,     av[mi], b0, b2);
                        mma16816(o + mi * 64 + nj * 8 + 4, av[mi], b1, b3);
                    }
                }
            }
        }
        // epilogue: O^T/l * gamma + ef  (inv depends on m = column)
        const float gm = gamma_p[0];
        if (tid < 256) invLs[tid2] = gm / Ls[tid2];
        bar256pv();
        const int c0 = (b << 8) + (pw << 5) + (lane >> 2);
        const int mb = (lane & 3) * 2;
#pragma unroll
        for (int mi = 0; mi < 2; mi++) {
            const size_t rowA = ((size_t)(c0 + mi * 16)) * NPIX + mtile;
            const size_t rowB = rowA + 8 * NPIX;
#pragma unroll
            for (int nj = 0; nj < 8; nj++)
#pragma unroll
                for (int half = 0; half < 2; half++) {
                    const int mm = nj * 16 + half * 8 + mb;
                    const float i0v = invLs[mm], i1v = invLs[mm + 1];
                    const int idx = mi * 64 + nj * 8 + half * 4;
                    out[rowA + mm]     = o[idx + 0] * i0v + ef[rowA + mm];
                    out[rowA + mm + 1] = o[idx + 1] * i1v + ef[rowA + mm + 1];
                    out[rowB + mm]     = o[idx + 2] * i0v + ef[rowB + mm];
                    out[rowB + mm + 1] = o[idx + 3] * i1v + ef[rowB + mm + 1];
                }
        }
    }
}

extern "C" void kernel_launch(void* const* d_in, const int* in_sizes, int n_in,
                              void* d_out, int out_size) {
    const float* ef = (const float*)d_in[0];
    const float* sf = (const float*)d_in[1];
    const float* At = (const float*)d_in[2];
    const float* Qw = (const float*)d_in[3];
    const float* Qb = (const float*)d_in[4];
    const float* Kw = (const float*)d_in[5];
    const float* Kb = (const float*)d_in[6];
    const float* Vw = (const float*)d_in[7];
    const float* Vb = (const float*)d_in[8];
    const float* gm = (const float*)d_in[9];
    float* out = (float*)d_out;

    cudaFuncSetAttribute(proj_kernel, cudaFuncAttributeMaxDynamicSharedMemorySize, PROJ_SMEM);
    cudaFuncSetAttribute(flash_kernel, cudaFuncAttributeMaxDynamicSharedMemorySize, FLASH_SMEM);

    prep_kernel<<<128, 256>>>(Qw, Kw, Vw);
    proj_kernel<<<dim3(32, 4), 256, PROJ_SMEM>>>(ef, sf, At, Qb, Kb, Vb);
    flash_kernel<<<dim3(32, 4), 384, FLASH_SMEM>>>(ef, gm, out);
}